// round 16
// baseline (speedup 1.0000x reference)
#include <cuda_runtime.h>
#include <cuda_fp16.h>
#include <cstdint>
#include <math.h>

#define BS    2
#define SEQ   2048
#define DEMB  1024
#define DATTN 1024
#define NH    16
#define HD    64
#define MROWS (BS*SEQ)   // 4096

#define LOG2E 1.4426950408889634f
#define QSCALE (0.125f * LOG2E)   // folded softmax scale (log2 domain)

// ---------------------------------------------------------------------------
// Scratch (device globals -- no allocation allowed)
// ---------------------------------------------------------------------------
__device__ __half g_xh[MROWS * DEMB];
__device__ __half g_wqh[DATTN * DEMB];
__device__ __half g_wkh[DATTN * DEMB];
__device__ __half g_wvh[DATTN * DEMB];
__device__ __half g_woh[DATTN * DATTN];
__device__ __half g_qh[MROWS * DATTN];
__device__ __half g_kh[MROWS * DATTN];
__device__ __half g_vh[MROWS * DATTN];
__device__ __half g_ch[MROWS * DATTN];

// ---------------------------------------------------------------------------
// PTX helpers
// ---------------------------------------------------------------------------
__device__ __forceinline__ uint32_t smem_u32(const void* p) {
    uint32_t a;
    asm("{ .reg .u64 t; cvta.to.shared.u64 t, %1; cvt.u32.u64 %0, t; }"
        : "=r"(a) : "l"(p));
    return a;
}

#define LDMATRIX_X4(r0, r1, r2, r3, addr) \
    asm volatile("ldmatrix.sync.aligned.m8n8.x4.shared.b16 {%0,%1,%2,%3}, [%4];" \
        : "=r"(r0), "=r"(r1), "=r"(r2), "=r"(r3) : "r"(addr))

#define LDMATRIX_X4T(r0, r1, r2, r3, addr) \
    asm volatile("ldmatrix.sync.aligned.m8n8.x4.trans.shared.b16 {%0,%1,%2,%3}, [%4];" \
        : "=r"(r0), "=r"(r1), "=r"(r2), "=r"(r3) : "r"(addr))

// fp32-accumulator MMA
#define MMA_F16(d, a, b) \
    asm volatile("mma.sync.aligned.m16n8k16.row.col.f32.f16.f16.f32 " \
        "{%0,%1,%2,%3}, {%4,%5,%6,%7}, {%8,%9}, {%0,%1,%2,%3};" \
        : "+f"((d)[0]), "+f"((d)[1]), "+f"((d)[2]), "+f"((d)[3]) \
        : "r"((a)[0]), "r"((a)[1]), "r"((a)[2]), "r"((a)[3]), \
          "r"((b)[0]), "r"((b)[1]))

// fp16-accumulator MMA (2x rate)
#define MMA_F16ACC(d, a, b) \
    asm volatile("mma.sync.aligned.m16n8k16.row.col.f16.f16.f16.f16 " \
        "{%0,%1}, {%2,%3,%4,%5}, {%6,%7}, {%0,%1};" \
        : "+r"((d)[0]), "+r"((d)[1]) \
        : "r"((a)[0]), "r"((a)[1]), "r"((a)[2]), "r"((a)[3]), \
          "r"((b)[0]), "r"((b)[1]))

#define CP_ASYNC16(saddr, gptr) \
    asm volatile("cp.async.cg.shared.global [%0], [%1], 16;" \
        :: "r"(saddr), "l"(gptr))
#define CP_COMMIT() asm volatile("cp.async.commit_group;" ::: "memory")
#define CP_WAIT(n)  asm volatile("cp.async.wait_group %0;" :: "n"(n) : "memory")

#define EX2_F16X2(out, in) \
    asm("ex2.approx.f16x2 %0, %1;" : "=r"(out) : "r"(in))

__device__ __forceinline__ uint32_t sw128(uint32_t bo) {
    return bo ^ ((bo >> 3) & 0x70);
}

__device__ __forceinline__ uint32_t pack_h2(float x, float y) {
    __half2 h = __floats2half2_rn(x, y);
    return *reinterpret_cast<uint32_t*>(&h);
}

// ---------------------------------------------------------------------------
// Fused fp32 -> fp16 convert: x + 4 weights, one launch. (unchanged)
// ---------------------------------------------------------------------------
__global__ __launch_bounds__(256) void split_all(
    const float* __restrict__ x,  __half* __restrict__ xh,
    const float* __restrict__ wq, __half* __restrict__ qh,
    const float* __restrict__ wk, __half* __restrict__ kh,
    const float* __restrict__ wv, __half* __restrict__ vh,
    const float* __restrict__ wo, __half* __restrict__ oh)
{
    int blk = blockIdx.x;
    const float* src;
    __half* hi;
    int local;
    if (blk < 4096) { src = x; hi = xh; local = blk; }
    else {
        int w = (blk - 4096) >> 10;
        local = (blk - 4096) & 1023;
        src = (w == 0) ? wq : (w == 1) ? wk : (w == 2) ? wv : wo;
        hi  = (w == 0) ? qh : (w == 1) ? kh : (w == 2) ? vh : oh;
    }
    int i = local * 1024 + threadIdx.x * 4;
    float4 v = *(const float4*)(src + i);
    *(uint2*)(hi + i) = make_uint2(pack_h2(v.x, v.y), pack_h2(v.z, v.w));
}

// ---------------------------------------------------------------------------
// Persistent HMMA fp16 GEMM: C = Ah*Bh. CTA 128x128, BK=64, 3x32KB stages,
// 256 thr / 8 warps (2x4), 2 CTAs/SM.
// NEW: f16acc mode -- per-kt fp16 accumulation chains (4 MMAs, 2x tensor
// rate) promoted into fp32 accumulators each kt. Used for QKV; O-proj
// keeps full fp32 accumulation.
// ---------------------------------------------------------------------------
#define GK 1024
#define NKT (GK / 64)     // 16
#define STG 32768u
#define NTM (MROWS / 128) // 32
#define NTN (DATTN / 128) // 8

__global__ __launch_bounds__(256, 2) void gemm_hmma(
    const __half* __restrict__ Ah,
    const __half* __restrict__ Bh0, const __half* __restrict__ Bh1,
    const __half* __restrict__ Bh2,
    const float* __restrict__ bias,
    float* __restrict__ Cf,
    __half* __restrict__ H0, __half* __restrict__ H1, __half* __restrict__ H2,
    int ntiles, int doScaleQ, int f16acc)
{
    extern __shared__ char smem[];
    const uint32_t sbase = smem_u32(smem);

    const int tid = threadIdx.x;
    const int wid = tid >> 5;
    const int lid = tid & 31;
    const int warp_m = wid >> 2;
    const int warp_n = wid & 3;

    const uint32_t a_row = warp_m * 64 + (lid & 15);
    const uint32_t a_cb  = (lid >> 4) * 16;
    const uint32_t b_mi  = lid >> 3;
    const uint32_t b_row = warp_n * 32 + (b_mi >> 1) * 8 + (lid & 7);
    const uint32_t b_cb  = (b_mi & 1) * 16;
    const int gi = lid >> 2;
    const int ti = lid & 3;

    for (int tile = blockIdx.x; tile < ntiles; tile += gridDim.x) {
        const int z  = tile >> 8;
        const int rm = tile & 255;
        const int m0 = (rm >> 3) * 128;
        const int n0 = (rm & 7) * 128;

        const __half* Bh = (z == 0) ? Bh0 : (z == 1) ? Bh1 : Bh2;
        __half* Hs = (z == 0) ? H0 : (z == 1) ? H1 : H2;

        auto load_stage = [&](int kt, int s) {
            const uint32_t so = sbase + s * STG;
#pragma unroll
            for (int it = 0; it < 8; it++) {
                int idx = it * 256 + tid;
                int t   = idx >> 10;
                int r   = (idx >> 3) & 127;
                int c   = idx & 7;
                uint32_t sw = sw128((uint32_t)(r * 128 + c * 16));
                size_t g = (size_t)((t ? n0 : m0) + r) * GK + kt * 64 + c * 8;
                CP_ASYNC16(so + t * 16384 + sw, (t ? Bh : Ah) + g);
            }
        };

        float acc[4][4][4];
#pragma unroll
        for (int i = 0; i < 4; i++)
#pragma unroll
            for (int j = 0; j < 4; j++)
#pragma unroll
                for (int r = 0; r < 4; r++) acc[i][j][r] = 0.0f;

        load_stage(0, 0); CP_COMMIT();
        load_stage(1, 1); CP_COMMIT();

        for (int kt = 0; kt < NKT; kt++) {
            if (kt + 1 < NKT) CP_WAIT(1); else CP_WAIT(0);
            __syncthreads();
            if (kt + 2 < NKT) {
                load_stage(kt + 2, (kt + 2) % 3);
                CP_COMMIT();
            }

            const uint32_t pAH = sbase + (kt % 3) * STG;
            const uint32_t pBH = pAH + 16384;

            if (f16acc) {
                // All B fragments for this kt (32 regs), then per-i fp16
                // accumulation chains promoted to fp32.
                uint32_t bhall[4][4][2];
#pragma unroll
                for (int ks = 0; ks < 4; ks++)
#pragma unroll
                    for (int j2 = 0; j2 < 2; j2++) {
                        uint32_t off = sw128((b_row + j2 * 16) * 128 + ks * 32 + b_cb);
                        uint32_t r0, r1, r2, r3;
                        LDMATRIX_X4(r0, r1, r2, r3, pBH + off);
                        bhall[ks][j2*2][0] = r0; bhall[ks][j2*2][1] = r1;
                        bhall[ks][j2*2+1][0] = r2; bhall[ks][j2*2+1][1] = r3;
                    }
#pragma unroll
                for (int i = 0; i < 4; i++) {
                    uint32_t hacc[4][2];
#pragma unroll
                    for (int j = 0; j < 4; j++) { hacc[j][0] = 0u; hacc[j][1] = 0u; }
#pragma unroll
                    for (int ks = 0; ks < 4; ks++) {
                        uint32_t ah[4];
                        uint32_t off = sw128((a_row + i * 16) * 128 + ks * 32 + a_cb);
                        LDMATRIX_X4(ah[0], ah[1], ah[2], ah[3], pAH + off);
#pragma unroll
                        for (int j = 0; j < 4; j++)
                            MMA_F16ACC(hacc[j], ah, bhall[ks][j]);
                    }
                    // promote fp16 chain -> fp32 accumulators
#pragma unroll
                    for (int j = 0; j < 4; j++) {
                        float2 lo = __half22float2(*(__half2*)&hacc[j][0]);
                        float2 hi = __half22float2(*(__half2*)&hacc[j][1]);
                        acc[i][j][0] += lo.x; acc[i][j][1] += lo.y;
                        acc[i][j][2] += hi.x; acc[i][j][3] += hi.y;
                    }
                }
            } else {
#pragma unroll
                for (int ks = 0; ks < 4; ks++) {
                    uint32_t bh[4][2];
#pragma unroll
                    for (int j2 = 0; j2 < 2; j2++) {
                        uint32_t off = sw128((b_row + j2 * 16) * 128 + ks * 32 + b_cb);
                        uint32_t r0, r1, r2, r3;
                        LDMATRIX_X4(r0, r1, r2, r3, pBH + off);
                        bh[j2*2][0] = r0; bh[j2*2][1] = r1;
                        bh[j2*2+1][0] = r2; bh[j2*2+1][1] = r3;
                    }
#pragma unroll
                    for (int i = 0; i < 4; i++) {
                        uint32_t ah[4];
                        uint32_t off = sw128((a_row + i * 16) * 128 + ks * 32 + a_cb);
                        LDMATRIX_X4(ah[0], ah[1], ah[2], ah[3], pAH + off);
#pragma unroll
                        for (int j = 0; j < 4; j++)
                            MMA_F16(acc[i][j], ah, bh[j]);
                    }
                }
            }
        }
        __syncthreads();

        const float sc = (doScaleQ && z == 0) ? QSCALE : 1.0f;
        float* Cs = (float*)smem;
#pragma unroll
        for (int i = 0; i < 4; i++)
#pragma unroll
            for (int j = 0; j < 4; j++) {
                int row = warp_m * 64 + i * 16 + gi;
                int col = warp_n * 32 + j * 8 + ti * 2;
                Cs[row * 132 + col]           = acc[i][j][0];
                Cs[row * 132 + col + 1]       = acc[i][j][1];
                Cs[(row + 8) * 132 + col]     = acc[i][j][2];
                Cs[(row + 8) * 132 + col + 1] = acc[i][j][3];
            }
        __syncthreads();

#pragma unroll
        for (int it = 0; it < 16; it++) {
            int idx = it * 256 + tid;
            int r   = idx >> 5;
            int c4  = (idx & 31) * 4;
            float4 v = *(float4*)(Cs + r * 132 + c4);
            size_t go = (size_t)(m0 + r) * DATTN + n0 + c4;
            if (Hs) {
                *(uint2*)(Hs + go) =
                    make_uint2(pack_h2(v.x * sc, v.y * sc),
                               pack_h2(v.z * sc, v.w * sc));
            } else {
                if (bias) {
                    float4 bv = *(const float4*)(bias + n0 + c4);
                    v.x += bv.x; v.y += bv.y; v.z += bv.z; v.w += bv.w;
                }
                *(float4*)(Cf + go) = v;
            }
        }
        __syncthreads();
    }
}

// ---------------------------------------------------------------------------
// HMMA fp16 causal flash attention (unchanged from round 14).
// ---------------------------------------------------------------------------
__global__ __launch_bounds__(256, 2) void attn_hmma(
    const __half* __restrict__ Qh,
    const __half* __restrict__ Kh,
    const __half* __restrict__ Vh,
    __half* __restrict__ Ch)
{
    extern __shared__ char smem[];
    const uint32_t sb = smem_u32(smem);
    const int tid = threadIdx.x, wid = tid >> 5, lid = tid & 31;
    const int gi = lid >> 2, ci = lid & 3;
    const int pi = blockIdx.x;
    const int h = blockIdx.y, b = blockIdx.z;

    const uint32_t ST = 16384, STSZ = 16384;

    const uint32_t a_row = wid * 16 + (lid & 15);
    const uint32_t a_cb  = (lid >> 4) * 16;
    const int b_mi = lid >> 3;
    const uint32_t b_rl = (uint32_t)((b_mi >> 1) * 8 + (lid & 7));
    const uint32_t b_cb = (uint32_t)((b_mi & 1) * 16);
    const uint32_t v_key = (uint32_t)(lid & 15);
    const uint32_t v_cb  = (uint32_t)((lid >> 4) * 16);

    const uint32_t ONES = 0x3C003C00u;
    const uint32_t ones_b[2] = {ONES, ONES};
    const uint32_t NINF2 = 0xFC00FC00u;

    const int NQT = SEQ / 128;

#pragma unroll 1
    for (int half = 0; half < 2; half++) {
        const int qt = half ? pi : (NQT - 1 - pi);

        if (half) __syncthreads();

        const size_t qbase = ((size_t)b * SEQ + (size_t)qt * 128) * DATTN + h * HD;

#pragma unroll
        for (int it = 0; it < 4; it++) {
            int idx = it * 256 + tid;
            int r = idx >> 3, c = idx & 7;
            uint32_t sw = sw128((uint32_t)(r * 128 + c * 16));
            CP_ASYNC16(sb + sw, Qh + qbase + (size_t)r * DATTN + c * 8);
        }
        CP_COMMIT();

        auto load_stage = [&](int kt) {
            uint32_t so = sb + ST + (uint32_t)(kt % 3) * STSZ;
            size_t kb = ((size_t)b * SEQ + (size_t)kt * 64) * DATTN + h * HD;
#pragma unroll
            for (int it = 0; it < 4; it++) {
                int idx = it * 256 + tid;
                int t = idx >> 9;
                int r = (idx >> 3) & 63;
                int c = idx & 7;
                uint32_t sw = sw128((uint32_t)(r * 128 + c * 16));
                size_t g = kb + (size_t)r * DATTN + c * 8;
                CP_ASYNC16(so + t * 8192 + sw, (t ? Vh : Kh) + g);
            }
        };
        load_stage(0); CP_COMMIT();
        load_stage(1); CP_COMMIT();

        CP_WAIT(2);
        __syncthreads();
        uint32_t qf[4][4];
#pragma unroll
        for (int ks = 0; ks < 4; ks++)
            LDMATRIX_X4(qf[ks][0], qf[ks][1], qf[ks][2], qf[ks][3],
                        sb + sw128(a_row * 128 + ks * 32 + a_cb));

        float oacc[8][4];
#pragma unroll
        for (int j = 0; j < 8; j++)
#pragma unroll
            for (int r = 0; r < 4; r++) oacc[j][r] = 0.0f;
        float lacc[4] = {0.f, 0.f, 0.f, 0.f};

        const int nkt = 2 * qt + 2;
        const int grow = qt * 128 + wid * 16 + gi;

        for (int kt = 0; kt < nkt; kt++) {
            if (kt + 1 < nkt) CP_WAIT(1); else CP_WAIT(0);
            __syncthreads();
            if (kt + 2 < nkt) {
                load_stage(kt + 2);
                CP_COMMIT();
            }

            const uint32_t pKH = sb + ST + (uint32_t)(kt % 3) * STSZ;
            const uint32_t pVH = pKH + 8192;

            uint32_t sacc[8][2];
#pragma unroll
            for (int j = 0; j < 8; j++) { sacc[j][0] = 0u; sacc[j][1] = 0u; }

#pragma unroll
            for (int ks = 0; ks < 4; ks++) {
#pragma unroll
                for (int j2 = 0; j2 < 4; j2++) {
                    uint32_t boff = sw128((j2 * 16 + b_rl) * 128 + ks * 32 + b_cb);
                    uint32_t h0, h1, h2, h3;
                    LDMATRIX_X4(h0, h1, h2, h3, pKH + boff);
                    uint32_t BH0[2] = {h0, h1}, BH1[2] = {h2, h3};
                    MMA_F16ACC(sacc[2*j2],   qf[ks], BH0);
                    MMA_F16ACC(sacc[2*j2+1], qf[ks], BH1);
                }
            }

            if (kt >= 2 * qt) {
#pragma unroll
                for (int j = 0; j < 8; j++)
#pragma unroll
                    for (int r2 = 0; r2 < 2; r2++) {
                        int c0  = kt * 64 + j * 8 + 2 * ci;
                        int row = grow + r2 * 8;
                        if (c0 > row)
                            sacc[j][r2] = NINF2;
                        else if (c0 + 1 > row)
                            sacc[j][r2] = (sacc[j][r2] & 0x0000FFFFu) | 0xFC000000u;
                    }
            }

#pragma unroll
            for (int ks = 0; ks < 4; ks++) {
                uint32_t phk[4];
                EX2_F16X2(phk[0], sacc[2*ks][0]);
                EX2_F16X2(phk[1], sacc[2*ks][1]);
                EX2_F16X2(phk[2], sacc[2*ks+1][0]);
                EX2_F16X2(phk[3], sacc[2*ks+1][1]);

                MMA_F16(lacc, phk, ones_b);

#pragma unroll
                for (int g = 0; g < 4; g++) {
                    uint32_t voff = sw128((ks * 16 + v_key) * 128 + g * 32 + v_cb);
                    uint32_t h0, h1, h2, h3;
                    LDMATRIX_X4T(h0, h1, h2, h3, pVH + voff);
                    uint32_t VH0[2] = {h0, h1}, VH1[2] = {h2, h3};
                    MMA_F16(oacc[2*g],   phk, VH0);
                    MMA_F16(oacc[2*g+1], phk, VH1);
                }
            }
        }

        const float inv0 = 1.0f / lacc[0];
        const float inv1 = 1.0f / lacc[2];
        const size_t ob0 = ((size_t)b * SEQ + grow) * DATTN + h * HD;
        const size_t ob1 = ob0 + (size_t)8 * DATTN;
#pragma unroll
        for (int jd = 0; jd < 8; jd++) {
            int col = jd * 8 + 2 * ci;
            *(uint32_t*)(Ch + ob0 + col) =
                pack_h2(oacc[jd][0] * inv0, oacc[jd][1] * inv0);
            *(uint32_t*)(Ch + ob1 + col) =
                pack_h2(oacc[jd][2] * inv1, oacc[jd][3] * inv1);
        }
    }
}

// ---------------------------------------------------------------------------
// Launch
// ---------------------------------------------------------------------------
extern "C" void kernel_launch(void* const* d_in, const int* in_sizes, int n_in,
                              void* d_out, int out_size)
{
    const float* x  = (const float*)d_in[0];
    const float* Wq = (const float*)d_in[1];
    const float* Wk = (const float*)d_in[2];
    const float* Wv = (const float*)d_in[3];
    const float* Wo = (const float*)d_in[4];
    const float* bo = (const float*)d_in[5];
    float* out = (float*)d_out;

    __half *xh, *wqh, *wkh, *wvh, *woh, *qh, *kh, *vh, *ch;
    cudaGetSymbolAddress((void**)&xh,  g_xh);
    cudaGetSymbolAddress((void**)&wqh, g_wqh);
    cudaGetSymbolAddress((void**)&wkh, g_wkh);
    cudaGetSymbolAddress((void**)&wvh, g_wvh);
    cudaGetSymbolAddress((void**)&woh, g_woh);
    cudaGetSymbolAddress((void**)&qh,  g_qh);
    cudaGetSymbolAddress((void**)&kh,  g_kh);
    cudaGetSymbolAddress((void**)&vh,  g_vh);
    cudaGetSymbolAddress((void**)&ch,  g_ch);

    split_all<<<8192, 256>>>(x, xh, Wq, wqh, Wk, wkh, Wv, wvh, Wo, woh);

    const int smem_gemm = 98304;   // 3 stages x 32KB
    cudaFuncSetAttribute(gemm_hmma, cudaFuncAttributeMaxDynamicSharedMemorySize,
                         smem_gemm);

    // QKV fused, persistent, fp16-chained accumulation (per-kt promote)
    gemm_hmma<<<296, 256, smem_gemm>>>(
        xh, wqh, wkh, wvh, nullptr, nullptr, qh, kh, vh,
        3 * NTM * NTN, /*doScaleQ=*/1, /*f16acc=*/1);

    // Attention: unchanged
    const int smem_att = 65536;    // Q 16K + 3 stages x 16K
    cudaFuncSetAttribute(attn_hmma, cudaFuncAttributeMaxDynamicSharedMemorySize,
                         smem_att);
    attn_hmma<<<dim3(SEQ / 256, NH, BS), 256, smem_att>>>(qh, kh, vh, ch);

    // Output projection, full fp32 accumulation (control / precision anchor)
    gemm_hmma<<<256, 256, smem_gemm>>>(
        ch, woh, nullptr, nullptr, bo, out, nullptr, nullptr, nullptr,
        NTM * NTN, /*doScaleQ=*/0, /*f16acc=*/0);
}

// round 17
// speedup vs baseline: 1.1975x; 1.1975x over previous
#include <cuda_runtime.h>
#include <cuda_fp16.h>
#include <cstdint>
#include <math.h>

#define BS    2
#define SEQ   2048
#define DEMB  1024
#define DATTN 1024
#define NH    16
#define HD    64
#define MROWS (BS*SEQ)   // 4096

#define LOG2E 1.4426950408889634f
#define QSCALE (0.125f * LOG2E)   // folded softmax scale (log2 domain)

// ---------------------------------------------------------------------------
// Scratch (device globals -- no allocation allowed)
// ---------------------------------------------------------------------------
__device__ __half g_xh[MROWS * DEMB];
__device__ __half g_wqh[DATTN * DEMB];
__device__ __half g_wkh[DATTN * DEMB];
__device__ __half g_wvh[DATTN * DEMB];
__device__ __half g_woh[DATTN * DATTN];
__device__ __half g_qh[MROWS * DATTN];
__device__ __half g_kh[MROWS * DATTN];
__device__ __half g_vh[MROWS * DATTN];
__device__ __half g_ch[MROWS * DATTN];

// ---------------------------------------------------------------------------
// PTX helpers
// ---------------------------------------------------------------------------
__device__ __forceinline__ uint32_t smem_u32(const void* p) {
    uint32_t a;
    asm("{ .reg .u64 t; cvta.to.shared.u64 t, %1; cvt.u32.u64 %0, t; }"
        : "=r"(a) : "l"(p));
    return a;
}

#define LDMATRIX_X4(r0, r1, r2, r3, addr) \
    asm volatile("ldmatrix.sync.aligned.m8n8.x4.shared.b16 {%0,%1,%2,%3}, [%4];" \
        : "=r"(r0), "=r"(r1), "=r"(r2), "=r"(r3) : "r"(addr))

#define LDMATRIX_X4T(r0, r1, r2, r3, addr) \
    asm volatile("ldmatrix.sync.aligned.m8n8.x4.trans.shared.b16 {%0,%1,%2,%3}, [%4];" \
        : "=r"(r0), "=r"(r1), "=r"(r2), "=r"(r3) : "r"(addr))

// fp32-accumulator MMA
#define MMA_F16(d, a, b) \
    asm volatile("mma.sync.aligned.m16n8k16.row.col.f32.f16.f16.f32 " \
        "{%0,%1,%2,%3}, {%4,%5,%6,%7}, {%8,%9}, {%0,%1,%2,%3};" \
        : "+f"((d)[0]), "+f"((d)[1]), "+f"((d)[2]), "+f"((d)[3]) \
        : "r"((a)[0]), "r"((a)[1]), "r"((a)[2]), "r"((a)[3]), \
          "r"((b)[0]), "r"((b)[1]))

// fp16-accumulator MMA (attention S only)
#define MMA_F16ACC(d, a, b) \
    asm volatile("mma.sync.aligned.m16n8k16.row.col.f16.f16.f16.f16 " \
        "{%0,%1}, {%2,%3,%4,%5}, {%6,%7}, {%0,%1};" \
        : "+r"((d)[0]), "+r"((d)[1]) \
        : "r"((a)[0]), "r"((a)[1]), "r"((a)[2]), "r"((a)[3]), \
          "r"((b)[0]), "r"((b)[1]))

#define CP_ASYNC16(saddr, gptr) \
    asm volatile("cp.async.cg.shared.global [%0], [%1], 16;" \
        :: "r"(saddr), "l"(gptr))
#define CP_COMMIT() asm volatile("cp.async.commit_group;" ::: "memory")
#define CP_WAIT(n)  asm volatile("cp.async.wait_group %0;" :: "n"(n) : "memory")

#define EX2_F16X2(out, in) \
    asm("ex2.approx.f16x2 %0, %1;" : "=r"(out) : "r"(in))

__device__ __forceinline__ uint32_t sw128(uint32_t bo) {
    return bo ^ ((bo >> 3) & 0x70);
}

__device__ __forceinline__ uint32_t pack_h2(float x, float y) {
    __half2 h = __floats2half2_rn(x, y);
    return *reinterpret_cast<uint32_t*>(&h);
}

// ---------------------------------------------------------------------------
// Fused fp32 -> fp16 convert: x + 4 weights, one launch. (unchanged)
// ---------------------------------------------------------------------------
__global__ __launch_bounds__(256) void split_all(
    const float* __restrict__ x,  __half* __restrict__ xh,
    const float* __restrict__ wq, __half* __restrict__ qh,
    const float* __restrict__ wk, __half* __restrict__ kh,
    const float* __restrict__ wv, __half* __restrict__ vh,
    const float* __restrict__ wo, __half* __restrict__ oh)
{
    int blk = blockIdx.x;
    const float* src;
    __half* hi;
    int local;
    if (blk < 4096) { src = x; hi = xh; local = blk; }
    else {
        int w = (blk - 4096) >> 10;
        local = (blk - 4096) & 1023;
        src = (w == 0) ? wq : (w == 1) ? wk : (w == 2) ? wv : wo;
        hi  = (w == 0) ? qh : (w == 1) ? kh : (w == 2) ? vh : oh;
    }
    int i = local * 1024 + threadIdx.x * 4;
    float4 v = *(const float4*)(src + i);
    *(uint2*)(hi + i) = make_uint2(pack_h2(v.x, v.y), pack_h2(v.z, v.w));
}

// ---------------------------------------------------------------------------
// Persistent HMMA fp16 GEMM: C = Ah*Bh. CTA 128x128, BK=64, fp32 accum.
// NEW: flattened (tile, kt) iteration with a CONTINUOUS 3-stage cp.async
//      pipeline across tile boundaries (no drain/refill bubble), and
//      direct fragment->global epilogue (no smem staging, no extra syncs).
// 256 thr / 8 warps (2x4), 2 CTAs/SM. smem = 3 x 32KB stages only.
// ---------------------------------------------------------------------------
#define GK 1024
#define NKT 16            // K-tiles per output tile (GK/64); power of 2
#define STG 32768u
#define NTM (MROWS / 128) // 32
#define NTN (DATTN / 128) // 8

__global__ __launch_bounds__(256, 2) void gemm_hmma(
    const __half* __restrict__ Ah,
    const __half* __restrict__ Bh0, const __half* __restrict__ Bh1,
    const __half* __restrict__ Bh2,
    const float* __restrict__ bias,
    float* __restrict__ Cf,
    __half* __restrict__ H0, __half* __restrict__ H1, __half* __restrict__ H2,
    int ntiles, int doScaleQ)
{
    extern __shared__ char smem[];
    const uint32_t sbase = smem_u32(smem);

    const int tid = threadIdx.x;
    const int wid = tid >> 5;
    const int lid = tid & 31;
    const int warp_m = wid >> 2;
    const int warp_n = wid & 3;

    const uint32_t a_row = warp_m * 64 + (lid & 15);
    const uint32_t a_cb  = (lid >> 4) * 16;
    const uint32_t b_mi  = lid >> 3;
    const uint32_t b_row = warp_n * 32 + (b_mi >> 1) * 8 + (lid & 7);
    const uint32_t b_cb  = (b_mi & 1) * 16;
    const int gi = lid >> 2;
    const int ti = lid & 3;

    // iterations this CTA owns: nloc tiles x NKT k-steps
    const int nloc  = (ntiles - blockIdx.x + gridDim.x - 1) / gridDim.x;
    const int niter = nloc * NKT;

    // load iteration u's K-tile into stage s
    auto load_iter = [&](int u, int s) {
        const int tile = blockIdx.x + (u >> 4) * gridDim.x;
        const int kt   = u & 15;
        const int z    = tile >> 8;
        const int rm   = tile & 255;
        const int m0   = (rm >> 3) * 128;
        const int n0   = (rm & 7) * 128;
        const __half* Bh = (z == 0) ? Bh0 : (z == 1) ? Bh1 : Bh2;
        const uint32_t so = sbase + (uint32_t)s * STG;
#pragma unroll
        for (int it = 0; it < 8; it++) {
            int idx = it * 256 + tid;
            int t   = idx >> 10;
            int r   = (idx >> 3) & 127;
            int c   = idx & 7;
            uint32_t sw = sw128((uint32_t)(r * 128 + c * 16));
            size_t g = (size_t)((t ? n0 : m0) + r) * GK + kt * 64 + c * 8;
            CP_ASYNC16(so + t * 16384 + sw, (t ? Bh : Ah) + g);
        }
    };

    float acc[4][4][4];
#pragma unroll
    for (int i = 0; i < 4; i++)
#pragma unroll
        for (int j = 0; j < 4; j++)
#pragma unroll
            for (int r = 0; r < 4; r++) acc[i][j][r] = 0.0f;

    load_iter(0, 0); CP_COMMIT();
    load_iter(1, 1); CP_COMMIT();   // niter >= 16 always

    int st = 0;        // stage of iteration u
    int stp = 2;       // stage of iteration u+2

    for (int u = 0; u < niter; u++) {
        if (u + 1 < niter) CP_WAIT(1); else CP_WAIT(0);
        __syncthreads();
        if (u + 2 < niter) {
            load_iter(u + 2, stp);
            CP_COMMIT();
        }

        const uint32_t pAH = sbase + (uint32_t)st * STG;
        const uint32_t pBH = pAH + 16384;

#pragma unroll
        for (int ks = 0; ks < 4; ks++) {
            uint32_t bh[4][2];
#pragma unroll
            for (int j2 = 0; j2 < 2; j2++) {
                uint32_t off = sw128((b_row + j2 * 16) * 128 + ks * 32 + b_cb);
                uint32_t r0, r1, r2, r3;
                LDMATRIX_X4(r0, r1, r2, r3, pBH + off);
                bh[j2*2][0] = r0; bh[j2*2][1] = r1;
                bh[j2*2+1][0] = r2; bh[j2*2+1][1] = r3;
            }
#pragma unroll
            for (int i = 0; i < 4; i++) {
                uint32_t ah[4];
                uint32_t off = sw128((a_row + i * 16) * 128 + ks * 32 + a_cb);
                LDMATRIX_X4(ah[0], ah[1], ah[2], ah[3], pAH + off);
#pragma unroll
                for (int j = 0; j < 4; j++)
                    MMA_F16(acc[i][j], ah, bh[j]);
            }
        }

        if ((u & 15) == 15) {
            // direct fragment -> global epilogue for the finished tile
            const int tile = blockIdx.x + (u >> 4) * gridDim.x;
            const int z    = tile >> 8;
            const int rm   = tile & 255;
            const int m0   = (rm >> 3) * 128;
            const int n0   = (rm & 7) * 128;
            __half* Hs = (z == 0) ? H0 : (z == 1) ? H1 : H2;

            if (Hs) {
                const float sc = (doScaleQ && z == 0) ? QSCALE : 1.0f;
#pragma unroll
                for (int i = 0; i < 4; i++)
#pragma unroll
                    for (int j = 0; j < 4; j++) {
                        size_t row = (size_t)(m0 + warp_m * 64 + i * 16 + gi);
                        int    col = n0 + warp_n * 32 + j * 8 + ti * 2;
                        *(uint32_t*)(Hs + row * DATTN + col) =
                            pack_h2(acc[i][j][0] * sc, acc[i][j][1] * sc);
                        *(uint32_t*)(Hs + (row + 8) * DATTN + col) =
                            pack_h2(acc[i][j][2] * sc, acc[i][j][3] * sc);
                    }
            } else {
#pragma unroll
                for (int i = 0; i < 4; i++)
#pragma unroll
                    for (int j = 0; j < 4; j++) {
                        size_t row = (size_t)(m0 + warp_m * 64 + i * 16 + gi);
                        int    col = n0 + warp_n * 32 + j * 8 + ti * 2;
                        float b0 = bias[col], b1 = bias[col + 1];
                        *(float2*)(Cf + row * DATTN + col) =
                            make_float2(acc[i][j][0] + b0, acc[i][j][1] + b1);
                        *(float2*)(Cf + (row + 8) * DATTN + col) =
                            make_float2(acc[i][j][2] + b0, acc[i][j][3] + b1);
                    }
            }
            // reset accumulators for the next tile
#pragma unroll
            for (int i = 0; i < 4; i++)
#pragma unroll
                for (int j = 0; j < 4; j++)
#pragma unroll
                    for (int r = 0; r < 4; r++) acc[i][j][r] = 0.0f;
        }

        st  = (st  == 2) ? 0 : st + 1;
        stp = (stp == 2) ? 0 : stp + 1;
    }
}

// ---------------------------------------------------------------------------
// HMMA fp16 causal flash attention (R14 proven version, unchanged).
// Br=128, Bc=64, D=64, 2 CTAs/SM; 3-stage K/V ring; fp16 S-acc;
// direct f16x2 exp; reg-resident Q; ones-MMA l; qt-paired grid.
// ---------------------------------------------------------------------------
__global__ __launch_bounds__(256, 2) void attn_hmma(
    const __half* __restrict__ Qh,
    const __half* __restrict__ Kh,
    const __half* __restrict__ Vh,
    __half* __restrict__ Ch)
{
    extern __shared__ char smem[];
    const uint32_t sb = smem_u32(smem);
    const int tid = threadIdx.x, wid = tid >> 5, lid = tid & 31;
    const int gi = lid >> 2, ci = lid & 3;
    const int pi = blockIdx.x;
    const int h = blockIdx.y, b = blockIdx.z;

    const uint32_t ST = 16384, STSZ = 16384;

    const uint32_t a_row = wid * 16 + (lid & 15);
    const uint32_t a_cb  = (lid >> 4) * 16;
    const int b_mi = lid >> 3;
    const uint32_t b_rl = (uint32_t)((b_mi >> 1) * 8 + (lid & 7));
    const uint32_t b_cb = (uint32_t)((b_mi & 1) * 16);
    const uint32_t v_key = (uint32_t)(lid & 15);
    const uint32_t v_cb  = (uint32_t)((lid >> 4) * 16);

    const uint32_t ONES = 0x3C003C00u;
    const uint32_t ones_b[2] = {ONES, ONES};
    const uint32_t NINF2 = 0xFC00FC00u;

    const int NQT = SEQ / 128;

#pragma unroll 1
    for (int half = 0; half < 2; half++) {
        const int qt = half ? pi : (NQT - 1 - pi);

        if (half) __syncthreads();

        const size_t qbase = ((size_t)b * SEQ + (size_t)qt * 128) * DATTN + h * HD;

#pragma unroll
        for (int it = 0; it < 4; it++) {
            int idx = it * 256 + tid;
            int r = idx >> 3, c = idx & 7;
            uint32_t sw = sw128((uint32_t)(r * 128 + c * 16));
            CP_ASYNC16(sb + sw, Qh + qbase + (size_t)r * DATTN + c * 8);
        }
        CP_COMMIT();

        auto load_stage = [&](int kt) {
            uint32_t so = sb + ST + (uint32_t)(kt % 3) * STSZ;
            size_t kb = ((size_t)b * SEQ + (size_t)kt * 64) * DATTN + h * HD;
#pragma unroll
            for (int it = 0; it < 4; it++) {
                int idx = it * 256 + tid;
                int t = idx >> 9;
                int r = (idx >> 3) & 63;
                int c = idx & 7;
                uint32_t sw = sw128((uint32_t)(r * 128 + c * 16));
                size_t g = kb + (size_t)r * DATTN + c * 8;
                CP_ASYNC16(so + t * 8192 + sw, (t ? Vh : Kh) + g);
            }
        };
        load_stage(0); CP_COMMIT();
        load_stage(1); CP_COMMIT();

        CP_WAIT(2);
        __syncthreads();
        uint32_t qf[4][4];
#pragma unroll
        for (int ks = 0; ks < 4; ks++)
            LDMATRIX_X4(qf[ks][0], qf[ks][1], qf[ks][2], qf[ks][3],
                        sb + sw128(a_row * 128 + ks * 32 + a_cb));

        float oacc[8][4];
#pragma unroll
        for (int j = 0; j < 8; j++)
#pragma unroll
            for (int r = 0; r < 4; r++) oacc[j][r] = 0.0f;
        float lacc[4] = {0.f, 0.f, 0.f, 0.f};

        const int nkt = 2 * qt + 2;
        const int grow = qt * 128 + wid * 16 + gi;

        for (int kt = 0; kt < nkt; kt++) {
            if (kt + 1 < nkt) CP_WAIT(1); else CP_WAIT(0);
            __syncthreads();
            if (kt + 2 < nkt) {
                load_stage(kt + 2);
                CP_COMMIT();
            }

            const uint32_t pKH = sb + ST + (uint32_t)(kt % 3) * STSZ;
            const uint32_t pVH = pKH + 8192;

            uint32_t sacc[8][2];
#pragma unroll
            for (int j = 0; j < 8; j++) { sacc[j][0] = 0u; sacc[j][1] = 0u; }

#pragma unroll
            for (int ks = 0; ks < 4; ks++) {
#pragma unroll
                for (int j2 = 0; j2 < 4; j2++) {
                    uint32_t boff = sw128((j2 * 16 + b_rl) * 128 + ks * 32 + b_cb);
                    uint32_t h0, h1, h2, h3;
                    LDMATRIX_X4(h0, h1, h2, h3, pKH + boff);
                    uint32_t BH0[2] = {h0, h1}, BH1[2] = {h2, h3};
                    MMA_F16ACC(sacc[2*j2],   qf[ks], BH0);
                    MMA_F16ACC(sacc[2*j2+1], qf[ks], BH1);
                }
            }

            if (kt >= 2 * qt) {
#pragma unroll
                for (int j = 0; j < 8; j++)
#pragma unroll
                    for (int r2 = 0; r2 < 2; r2++) {
                        int c0  = kt * 64 + j * 8 + 2 * ci;
                        int row = grow + r2 * 8;
                        if (c0 > row)
                            sacc[j][r2] = NINF2;
                        else if (c0 + 1 > row)
                            sacc[j][r2] = (sacc[j][r2] & 0x0000FFFFu) | 0xFC000000u;
                    }
            }

#pragma unroll
            for (int ks = 0; ks < 4; ks++) {
                uint32_t phk[4];
                EX2_F16X2(phk[0], sacc[2*ks][0]);
                EX2_F16X2(phk[1], sacc[2*ks][1]);
                EX2_F16X2(phk[2], sacc[2*ks+1][0]);
                EX2_F16X2(phk[3], sacc[2*ks+1][1]);

                MMA_F16(lacc, phk, ones_b);

#pragma unroll
                for (int g = 0; g < 4; g++) {
                    uint32_t voff = sw128((ks * 16 + v_key) * 128 + g * 32 + v_cb);
                    uint32_t h0, h1, h2, h3;
                    LDMATRIX_X4T(h0, h1, h2, h3, pVH + voff);
                    uint32_t VH0[2] = {h0, h1}, VH1[2] = {h2, h3};
                    MMA_F16(oacc[2*g],   phk, VH0);
                    MMA_F16(oacc[2*g+1], phk, VH1);
                }
            }
        }

        const float inv0 = 1.0f / lacc[0];
        const float inv1 = 1.0f / lacc[2];
        const size_t ob0 = ((size_t)b * SEQ + grow) * DATTN + h * HD;
        const size_t ob1 = ob0 + (size_t)8 * DATTN;
#pragma unroll
        for (int jd = 0; jd < 8; jd++) {
            int col = jd * 8 + 2 * ci;
            *(uint32_t*)(Ch + ob0 + col) =
                pack_h2(oacc[jd][0] * inv0, oacc[jd][1] * inv0);
            *(uint32_t*)(Ch + ob1 + col) =
                pack_h2(oacc[jd][2] * inv1, oacc[jd][3] * inv1);
        }
    }
}

// ---------------------------------------------------------------------------
// Launch
// ---------------------------------------------------------------------------
extern "C" void kernel_launch(void* const* d_in, const int* in_sizes, int n_in,
                              void* d_out, int out_size)
{
    const float* x  = (const float*)d_in[0];
    const float* Wq = (const float*)d_in[1];
    const float* Wk = (const float*)d_in[2];
    const float* Wv = (const float*)d_in[3];
    const float* Wo = (const float*)d_in[4];
    const float* bo = (const float*)d_in[5];
    float* out = (float*)d_out;

    __half *xh, *wqh, *wkh, *wvh, *woh, *qh, *kh, *vh, *ch;
    cudaGetSymbolAddress((void**)&xh,  g_xh);
    cudaGetSymbolAddress((void**)&wqh, g_wqh);
    cudaGetSymbolAddress((void**)&wkh, g_wkh);
    cudaGetSymbolAddress((void**)&wvh, g_wvh);
    cudaGetSymbolAddress((void**)&woh, g_woh);
    cudaGetSymbolAddress((void**)&qh,  g_qh);
    cudaGetSymbolAddress((void**)&kh,  g_kh);
    cudaGetSymbolAddress((void**)&vh,  g_vh);
    cudaGetSymbolAddress((void**)&ch,  g_ch);

    split_all<<<8192, 256>>>(x, xh, Wq, wqh, Wk, wkh, Wv, wvh, Wo, woh);

    const int smem_gemm = 98304;   // 3 stages x 32KB
    cudaFuncSetAttribute(gemm_hmma, cudaFuncAttributeMaxDynamicSharedMemorySize,
                         smem_gemm);

    // QKV fused, persistent, continuous pipeline: 768 tiles on 296 CTAs
    gemm_hmma<<<296, 256, smem_gemm>>>(
        xh, wqh, wkh, wvh, nullptr, nullptr, qh, kh, vh,
        3 * NTM * NTN, /*doScaleQ=*/1);

    // Attention (R14 config)
    const int smem_att = 65536;    // Q 16K + 3 stages x 16K
    cudaFuncSetAttribute(attn_hmma, cudaFuncAttributeMaxDynamicSharedMemorySize,
                         smem_att);
    attn_hmma<<<dim3(SEQ / 256, NH, BS), 256, smem_att>>>(qh, kh, vh, ch);

    // Output projection, fp32 + bias (direct-store epilogue)
    gemm_hmma<<<256, 256, smem_gemm>>>(
        ch, woh, nullptr, nullptr, bo, out, nullptr, nullptr, nullptr,
        NTM * NTN, /*doScaleQ=*/0);
}